// round 1
// baseline (speedup 1.0000x reference)
#include <cuda_runtime.h>

#define NN 50000
#define NE 800000
#define DD 128
#define ND (NN * DD)          // 6,400,000
#define LSLOPE 0.01f
#define BN_EPS 1e-5f

// ---------------- scratch (device globals; no allocation allowed) ----------
__device__ float g_embs[4 * ND];   // evolving embeddings per relation type
__device__ float g_H[ND];          // GEMM output h = (x * c_src) @ W
__device__ float g_AGG[ND];        // scatter-add accumulator
__device__ float g_csrc[4 * NN];
__device__ float g_cdst[4 * NN];
__device__ int   g_deg[8 * NN];    // [t][out/in][node]
__device__ float g_rels[4 * DD];   // evolving relation vectors
__device__ float g_stats[2 * DD];  // BN column sum / sumsq

// ---------------- zero kernels --------------------------------------------
__global__ void k_zero_deg() {
    int i = blockIdx.x * 256 + threadIdx.x;
    if (i < 8 * NN) g_deg[i] = 0;
}
__global__ void k_zero_agg() {
    int i = blockIdx.x * 256 + threadIdx.x;
    if (i < ND / 4) ((float4*)g_AGG)[i] = make_float4(0.f, 0.f, 0.f, 0.f);
}
__global__ void k_zero_stats() {
    int i = threadIdx.x;
    if (i < 2 * DD) g_stats[i] = 0.f;
}

// ---------------- degrees + normalization coeffs --------------------------
__global__ void k_deg(const int* __restrict__ e0, const int* __restrict__ e1,
                      const int* __restrict__ e2, const int* __restrict__ e3) {
    int gid = blockIdx.x * 256 + threadIdx.x;
    if (gid >= 4 * NE) return;
    int t = gid / NE;
    int e = gid - t * NE;
    const int* ei = (t == 0) ? e0 : (t == 1) ? e1 : (t == 2) ? e2 : e3;
    atomicAdd(&g_deg[t * 2 * NN + ei[e]], 1);            // out-degree of src
    atomicAdd(&g_deg[t * 2 * NN + NN + ei[NE + e]], 1);  // in-degree of dst
}
__global__ void k_c() {
    int gid = blockIdx.x * 256 + threadIdx.x;
    if (gid >= 4 * NN) return;
    int t = gid / NN, v = gid - t * NN;
    int dout = g_deg[t * 2 * NN + v];
    int din  = g_deg[t * 2 * NN + NN + v];
    g_csrc[t * NN + v] = dout > 0 ? rsqrtf((float)dout) : 1.0f;
    g_cdst[t * NN + v] = din  > 0 ? rsqrtf((float)din)  : 1.0f;
}

// ---------------- init ----------------------------------------------------
__global__ void k_init(const float* __restrict__ feat) {
    int i = blockIdx.x * 256 + threadIdx.x;
    if (i >= ND / 4) return;
    float4 v = ((const float4*)feat)[i];
    ((float4*)g_embs)[0 * (ND / 4) + i] = v;
    ((float4*)g_embs)[1 * (ND / 4) + i] = v;
    ((float4*)g_embs)[2 * (ND / 4) + i] = v;
    ((float4*)g_embs)[3 * (ND / 4) + i] = v;
}
__global__ void k_relinit(const float* __restrict__ r0, const float* __restrict__ r1,
                          const float* __restrict__ r2, const float* __restrict__ r3) {
    int tid = threadIdx.x;
    if (tid >= 512) return;
    int t = tid >> 7, d = tid & 127;
    const float* r = (t == 0) ? r0 : (t == 1) ? r1 : (t == 2) ? r2 : r3;
    g_rels[t * DD + d] = r[d];
}

// ---------------- fused-scale GEMM: g_H = (embs_t * rel_t * c_src) @ W ----
// 256 threads, 64-row x 128-col tile, 4x8 micro-tile/thread, K chunks of 32.
__global__ void __launch_bounds__(256) k_gemm(int t, const float* __restrict__ W) {
    __shared__ float As[64 * 32];
    __shared__ float Bs[32 * 128];
    __shared__ float srel[128];
    const float* X  = g_embs + (long)t * ND;
    const float* cs = g_csrc + t * NN;
    const int tid = threadIdx.x;
    const int rb  = blockIdx.x * 64;
    const int tx  = tid & 15, ty = tid >> 4;
    if (tid < 128) srel[tid] = g_rels[t * DD + tid];

    float acc[4][8];
#pragma unroll
    for (int i = 0; i < 4; i++)
#pragma unroll
        for (int j = 0; j < 8; j++) acc[i][j] = 0.f;

    for (int kc = 0; kc < 128; kc += 32) {
        __syncthreads();  // also guards srel on first iter
#pragma unroll
        for (int u = 0; u < 2; u++) {
            int idx = tid + u * 256;          // 0..511 float4 slots
            int r   = idx >> 3;
            int c4  = (idx & 7) * 4;
            int row = rb + r;
            float4 v = make_float4(0.f, 0.f, 0.f, 0.f);
            if (row < NN) {
                v = *(const float4*)(X + row * 128 + kc + c4);
                float c = cs[row];
                v.x *= c * srel[kc + c4 + 0];
                v.y *= c * srel[kc + c4 + 1];
                v.z *= c * srel[kc + c4 + 2];
                v.w *= c * srel[kc + c4 + 3];
            }
            *(float4*)&As[r * 32 + c4] = v;
        }
#pragma unroll
        for (int u = 0; u < 4; u++) {
            int idx = tid + u * 256;          // 0..1023 float4 slots
            int r   = idx >> 5;
            int c4  = (idx & 31) * 4;
            *(float4*)&Bs[r * 128 + c4] = *(const float4*)(W + (kc + r) * 128 + c4);
        }
        __syncthreads();
#pragma unroll
        for (int k = 0; k < 32; k++) {
            float a0 = As[(ty * 4 + 0) * 32 + k];
            float a1 = As[(ty * 4 + 1) * 32 + k];
            float a2 = As[(ty * 4 + 2) * 32 + k];
            float a3 = As[(ty * 4 + 3) * 32 + k];
            float b[8];
            *(float4*)&b[0] = *(float4*)&Bs[k * 128 + tx * 4];
            *(float4*)&b[4] = *(float4*)&Bs[k * 128 + 64 + tx * 4];
#pragma unroll
            for (int j = 0; j < 8; j++) {
                acc[0][j] += a0 * b[j];
                acc[1][j] += a1 * b[j];
                acc[2][j] += a2 * b[j];
                acc[3][j] += a3 * b[j];
            }
        }
    }
#pragma unroll
    for (int i = 0; i < 4; i++) {
        int row = rb + ty * 4 + i;
        if (row < NN) {
            *(float4*)(g_H + row * 128 + tx * 4) =
                make_float4(acc[i][0], acc[i][1], acc[i][2], acc[i][3]);
            *(float4*)(g_H + row * 128 + 64 + tx * 4) =
                make_float4(acc[i][4], acc[i][5], acc[i][6], acc[i][7]);
        }
    }
}

// ---------------- edge scatter-add: g_AGG[dst] += g_H[src] ----------------
// One warp per edge; lane l handles 4 contiguous floats (512B/edge, coalesced).
__global__ void __launch_bounds__(256) k_scatter(const int* __restrict__ src,
                                                 const int* __restrict__ dst) {
    int gid  = blockIdx.x * 256 + threadIdx.x;
    int e    = gid >> 5;
    int lane = gid & 31;
    if (e >= NE) return;
    int s = __ldg(src + e);
    int d = __ldg(dst + e);
    float4 v = *(const float4*)(g_H + (long)s * 128 + lane * 4);
    float* a = g_AGG + (long)d * 128 + lane * 4;
    atomicAdd(a + 0, v.x);
    atomicAdd(a + 1, v.y);
    atomicAdd(a + 2, v.z);
    atomicAdd(a + 3, v.w);
}

// ---------------- BN column stats over y = agg*c_dst + b ------------------
__global__ void k_stats(int t, const float* __restrict__ b) {
    const float* cd = g_cdst + t * NN;
    int tid  = threadIdx.x;
    int col  = tid & 127;
    int base = blockIdx.x * 256;
    int end  = min(base + 256, NN);
    float s = 0.f, s2 = 0.f;
    float bc = b[col];
    for (int r = base + (tid >> 7); r < end; r += 2) {
        float y = g_AGG[(long)r * 128 + col] * cd[r] + bc;
        s += y;
        s2 += y * y;
    }
    __shared__ float sh[512];
    sh[tid] = s;
    sh[256 + tid] = s2;
    __syncthreads();
    if (tid < 128) {
        atomicAdd(&g_stats[col],       sh[tid] + sh[tid + 128]);
        atomicAdd(&g_stats[128 + col], sh[256 + tid] + sh[256 + tid + 128]);
    }
}

// ---------------- BN normalize + leaky-relu residual into embs ------------
__global__ void k_norm(int t, const float* __restrict__ b,
                       const float* __restrict__ gamma, const float* __restrict__ beta) {
    int gid = blockIdx.x * 256 + threadIdx.x;
    if (gid >= ND) return;
    int v = gid >> 7, c = gid & 127;
    float y   = g_AGG[gid] * g_cdst[t * NN + v] + b[c];
    float mu  = g_stats[c] * (1.0f / NN);
    float var = g_stats[128 + c] * (1.0f / NN) - mu * mu;
    float h   = (y - mu) * rsqrtf(var + BN_EPS) * gamma[c] + beta[c];
    h = h > 0.f ? h : LSLOPE * h;
    g_embs[(long)t * ND + gid] += h;
}

// ---------------- final conv epilogue -> d_out ----------------------------
__global__ void k_finish(int t, const float* __restrict__ b, float* __restrict__ out) {
    int gid = blockIdx.x * 256 + threadIdx.x;
    if (gid >= ND) return;
    int v = gid >> 7, c = gid & 127;
    out[gid] = g_AGG[gid] * g_cdst[t * NN + v] + b[c];
}

// ---------------- relation vector update: rel' = rel @ Wr^T + br ----------
__global__ void k_relupd(int t, const float* __restrict__ Wr, const float* __restrict__ br) {
    __shared__ float sr[128];
    int d = threadIdx.x;
    sr[d] = g_rels[t * DD + d];
    __syncthreads();
    float s = br[d];
#pragma unroll
    for (int k = 0; k < 128; k++) s += sr[k] * Wr[d * 128 + k];
    g_rels[t * DD + d] = s;
}
__global__ void k_relout(int t, const float* __restrict__ Wr, const float* __restrict__ br,
                         float* __restrict__ out) {
    __shared__ float sr[128];
    int d = threadIdx.x;
    sr[d] = g_rels[t * DD + d];
    __syncthreads();
    float s = br[d];
#pragma unroll
    for (int k = 0; k < 128; k++) s += sr[k] * Wr[d * 128 + k];
    out[d] = s;
}

// ---------------- host orchestration --------------------------------------
extern "C" void kernel_launch(void* const* d_in, const int* in_sizes, int n_in,
                              void* d_out, int out_size) {
    const float* feat = (const float*)d_in[0];
    const float* r0 = (const float*)d_in[1];
    const float* r1 = (const float*)d_in[2];
    const float* r2 = (const float*)d_in[3];
    const float* r3 = (const float*)d_in[4];
    const int* eix[4] = {(const int*)d_in[5], (const int*)d_in[6],
                         (const int*)d_in[7], (const int*)d_in[8]};
    const float* gW  = (const float*)d_in[9];
    const float* gb  = (const float*)d_in[10];
    const float* bng = (const float*)d_in[11];
    const float* bnb = (const float*)d_in[12];
    const float* rW  = (const float*)d_in[13];
    const float* rb_ = (const float*)d_in[14];
    float* out = (float*)d_out;

    // degrees + norm coefficients (edges are inputs; recompute every call)
    k_zero_deg<<<(8 * NN + 255) / 256, 256>>>();
    k_deg<<<(4 * NE + 255) / 256, 256>>>(eix[0], eix[1], eix[2], eix[3]);
    k_c<<<(4 * NN + 255) / 256, 256>>>();

    // init evolving state
    k_init<<<(ND / 4 + 255) / 256, 256>>>(feat);
    k_relinit<<<1, 512>>>(r0, r1, r2, r3);

    const int GEMM_BLOCKS = (NN + 63) / 64;       // 782
    const int SCAT_BLOCKS = (NE * 32) / 256;      // 100000
    const int ELEM_BLOCKS = (ND + 255) / 256;     // 25000
    const int STAT_BLOCKS = (NN + 255) / 256;     // 196
    const int ZAGG_BLOCKS = (ND / 4 + 255) / 256; // 6250

    for (int i = 0; i < 2; i++) {
        for (int t = 0; t < 4; t++) {
            k_gemm<<<GEMM_BLOCKS, 256>>>(t, gW + i * DD * DD);
            k_zero_agg<<<ZAGG_BLOCKS, 256>>>();
            k_scatter<<<SCAT_BLOCKS, 256>>>(eix[t], eix[t] + NE);
            k_zero_stats<<<1, 256>>>();
            k_stats<<<STAT_BLOCKS, 256>>>(t, gb + i * DD);
            k_norm<<<ELEM_BLOCKS, 256>>>(t, gb + i * DD, bng + i * DD, bnb + i * DD);
            k_relupd<<<1, 128>>>(t, rW + i * DD * DD, rb_ + i * DD);
        }
    }
    // final layer
    for (int t = 0; t < 4; t++) {
        k_gemm<<<GEMM_BLOCKS, 256>>>(t, gW + 2 * DD * DD);
        k_zero_agg<<<ZAGG_BLOCKS, 256>>>();
        k_scatter<<<SCAT_BLOCKS, 256>>>(eix[t], eix[t] + NE);
        k_finish<<<ELEM_BLOCKS, 256>>>(t, gb + 2 * DD, out + (long)t * ND);
        k_relout<<<1, 128>>>(t, rW + 2 * DD * DD, rb_ + 2 * DD,
                             out + 4L * ND + t * DD);
    }
}

// round 2
// speedup vs baseline: 1.4728x; 1.4728x over previous
#include <cuda_runtime.h>

#define NN 50000
#define NE 800000
#define DD 128
#define ND (NN * DD)          // 6,400,000
#define LSLOPE 0.01f
#define BN_EPS 1e-5f

// ---------------- scratch (device globals; no allocation allowed) ----------
__device__ float g_embs[4 * ND];   // evolving embeddings per relation type
__device__ float g_H[ND];          // GEMM output h = (x * c_src) @ W
__device__ float g_AGG[ND];        // scatter-add accumulator
__device__ float g_csrc[4 * NN];
__device__ float g_cdst[4 * NN];
__device__ int   g_deg[8 * NN];    // [t][out/in][node]
__device__ float g_rels[4 * DD];   // evolving relation vectors
__device__ float g_stats[2 * DD];  // BN column sum / sumsq

// ---------------- zero kernels --------------------------------------------
__global__ void k_zero_deg() {
    int i = blockIdx.x * 256 + threadIdx.x;
    if (i < 8 * NN) g_deg[i] = 0;
}
__global__ void k_zero_agg() {
    int i = blockIdx.x * 256 + threadIdx.x;
    if (i < ND / 4) ((float4*)g_AGG)[i] = make_float4(0.f, 0.f, 0.f, 0.f);
}
__global__ void k_zero_stats() {
    int i = threadIdx.x;
    if (i < 2 * DD) g_stats[i] = 0.f;
}

// ---------------- degrees + normalization coeffs --------------------------
__global__ void k_deg(const int* __restrict__ e0, const int* __restrict__ e1,
                      const int* __restrict__ e2, const int* __restrict__ e3) {
    int gid = blockIdx.x * 256 + threadIdx.x;
    if (gid >= 4 * NE) return;
    int t = gid / NE;
    int e = gid - t * NE;
    const int* ei = (t == 0) ? e0 : (t == 1) ? e1 : (t == 2) ? e2 : e3;
    atomicAdd(&g_deg[t * 2 * NN + ei[e]], 1);            // out-degree of src
    atomicAdd(&g_deg[t * 2 * NN + NN + ei[NE + e]], 1);  // in-degree of dst
}
__global__ void k_c() {
    int gid = blockIdx.x * 256 + threadIdx.x;
    if (gid >= 4 * NN) return;
    int t = gid / NN, v = gid - t * NN;
    int dout = g_deg[t * 2 * NN + v];
    int din  = g_deg[t * 2 * NN + NN + v];
    g_csrc[t * NN + v] = dout > 0 ? rsqrtf((float)dout) : 1.0f;
    g_cdst[t * NN + v] = din  > 0 ? rsqrtf((float)din)  : 1.0f;
}

// ---------------- init ----------------------------------------------------
__global__ void k_init(const float* __restrict__ feat) {
    int i = blockIdx.x * 256 + threadIdx.x;
    if (i >= ND / 4) return;
    float4 v = ((const float4*)feat)[i];
    ((float4*)g_embs)[0 * (ND / 4) + i] = v;
    ((float4*)g_embs)[1 * (ND / 4) + i] = v;
    ((float4*)g_embs)[2 * (ND / 4) + i] = v;
    ((float4*)g_embs)[3 * (ND / 4) + i] = v;
}
__global__ void k_relinit(const float* __restrict__ r0, const float* __restrict__ r1,
                          const float* __restrict__ r2, const float* __restrict__ r3) {
    int tid = threadIdx.x;
    if (tid >= 512) return;
    int t = tid >> 7, d = tid & 127;
    const float* r = (t == 0) ? r0 : (t == 1) ? r1 : (t == 2) ? r2 : r3;
    g_rels[t * DD + d] = r[d];
}

// ---------------- fused-scale GEMM: g_H = (embs_t * rel_t * c_src) @ W ----
// 256 threads, 128x128 block tile, 8x8 micro-tile/thread, K chunks of 16.
__global__ void __launch_bounds__(256) k_gemm(int t, const float* __restrict__ W) {
    __shared__ float As[128 * 16];    // [m][k]
    __shared__ float Bs[16 * 128];    // [k][n]
    __shared__ float srel[128];
    const float* X  = g_embs + (long)t * ND;
    const float* cs = g_csrc + t * NN;
    const int tid = threadIdx.x;
    const int rb  = blockIdx.x * 128;
    const int tx  = tid & 15, ty = tid >> 4;   // 16 x 16 thread grid
    if (tid < 128) srel[tid] = g_rels[t * DD + tid];

    float acc[8][8];
#pragma unroll
    for (int i = 0; i < 8; i++)
#pragma unroll
        for (int j = 0; j < 8; j++) acc[i][j] = 0.f;

    for (int kc = 0; kc < 128; kc += 16) {
        __syncthreads();  // also guards srel on first iter
        // load As: 128 rows x 16 k = 512 float4 slots, 2 per thread (scaled)
#pragma unroll
        for (int u = 0; u < 2; u++) {
            int idx = tid + u * 256;          // 0..511
            int r   = idx >> 2;               // row within tile
            int c4  = (idx & 3) * 4;          // k offset
            int row = rb + r;
            float4 v = make_float4(0.f, 0.f, 0.f, 0.f);
            if (row < NN) {
                v = *(const float4*)(X + (long)row * 128 + kc + c4);
                float c = cs[row];
                v.x *= c * srel[kc + c4 + 0];
                v.y *= c * srel[kc + c4 + 1];
                v.z *= c * srel[kc + c4 + 2];
                v.w *= c * srel[kc + c4 + 3];
            }
            *(float4*)&As[r * 16 + c4] = v;
        }
        // load Bs: 16 x 128 = 512 float4 slots, 2 per thread
#pragma unroll
        for (int u = 0; u < 2; u++) {
            int idx = tid + u * 256;          // 0..511
            int r   = idx >> 5;               // k row
            int c4  = (idx & 31) * 4;         // n offset
            *(float4*)&Bs[r * 128 + c4] = *(const float4*)(W + (long)(kc + r) * 128 + c4);
        }
        __syncthreads();
#pragma unroll
        for (int k = 0; k < 16; k++) {
            float a[8], b[8];
#pragma unroll
            for (int i = 0; i < 8; i++) a[i] = As[(ty * 8 + i) * 16 + k];
            *(float4*)&b[0] = *(float4*)&Bs[k * 128 + tx * 8];
            *(float4*)&b[4] = *(float4*)&Bs[k * 128 + tx * 8 + 4];
#pragma unroll
            for (int i = 0; i < 8; i++)
#pragma unroll
                for (int j = 0; j < 8; j++) acc[i][j] += a[i] * b[j];
        }
    }
#pragma unroll
    for (int i = 0; i < 8; i++) {
        int row = rb + ty * 8 + i;
        if (row < NN) {
            *(float4*)(g_H + (long)row * 128 + tx * 8) =
                make_float4(acc[i][0], acc[i][1], acc[i][2], acc[i][3]);
            *(float4*)(g_H + (long)row * 128 + tx * 8 + 4) =
                make_float4(acc[i][4], acc[i][5], acc[i][6], acc[i][7]);
        }
    }
}

// ---------------- edge scatter-add: g_AGG[dst] += g_H[src] ----------------
// One warp per edge; lane l handles 4 contiguous floats via one v4 reduction.
__global__ void __launch_bounds__(256) k_scatter(const int* __restrict__ src,
                                                 const int* __restrict__ dst) {
    int gid  = blockIdx.x * 256 + threadIdx.x;
    int e    = gid >> 5;
    int lane = gid & 31;
    if (e >= NE) return;
    int s = __ldg(src + e);
    int d = __ldg(dst + e);
    float4 v = *(const float4*)(g_H + (long)s * 128 + lane * 4);
    float* a = g_AGG + (long)d * 128 + lane * 4;
    asm volatile("red.global.add.v4.f32 [%0], {%1, %2, %3, %4};"
                 :: "l"(a), "f"(v.x), "f"(v.y), "f"(v.z), "f"(v.w)
                 : "memory");
}

// ---------------- BN column stats over y = agg*c_dst + b ------------------
__global__ void k_stats(int t, const float* __restrict__ b) {
    const float* cd = g_cdst + t * NN;
    int tid  = threadIdx.x;
    int col  = tid & 127;
    int base = blockIdx.x * 256;
    int end  = min(base + 256, NN);
    float s = 0.f, s2 = 0.f;
    float bc = b[col];
    for (int r = base + (tid >> 7); r < end; r += 2) {
        float y = g_AGG[(long)r * 128 + col] * cd[r] + bc;
        s += y;
        s2 += y * y;
    }
    __shared__ float sh[512];
    sh[tid] = s;
    sh[256 + tid] = s2;
    __syncthreads();
    if (tid < 128) {
        atomicAdd(&g_stats[col],       sh[tid] + sh[tid + 128]);
        atomicAdd(&g_stats[128 + col], sh[256 + tid] + sh[256 + tid + 128]);
    }
}

// ---------------- BN normalize + leaky-relu residual into embs ------------
__global__ void k_norm(int t, const float* __restrict__ b,
                       const float* __restrict__ gamma, const float* __restrict__ beta) {
    int gid = blockIdx.x * 256 + threadIdx.x;
    if (gid >= ND) return;
    int v = gid >> 7, c = gid & 127;
    float y   = g_AGG[gid] * g_cdst[t * NN + v] + b[c];
    float mu  = g_stats[c] * (1.0f / NN);
    float var = g_stats[128 + c] * (1.0f / NN) - mu * mu;
    float h   = (y - mu) * rsqrtf(var + BN_EPS) * gamma[c] + beta[c];
    h = h > 0.f ? h : LSLOPE * h;
    g_embs[(long)t * ND + gid] += h;
}

// ---------------- final conv epilogue -> d_out ----------------------------
__global__ void k_finish(int t, const float* __restrict__ b, float* __restrict__ out) {
    int gid = blockIdx.x * 256 + threadIdx.x;
    if (gid >= ND) return;
    int v = gid >> 7, c = gid & 127;
    out[gid] = g_AGG[gid] * g_cdst[t * NN + v] + b[c];
}

// ---------------- relation vector update: rel' = rel @ Wr^T + br ----------
__global__ void k_relupd(int t, const float* __restrict__ Wr, const float* __restrict__ br) {
    __shared__ float sr[128];
    int d = threadIdx.x;
    sr[d] = g_rels[t * DD + d];
    __syncthreads();
    float s = br[d];
#pragma unroll
    for (int k = 0; k < 128; k++) s += sr[k] * Wr[d * 128 + k];
    g_rels[t * DD + d] = s;
}
__global__ void k_relout(int t, const float* __restrict__ Wr, const float* __restrict__ br,
                         float* __restrict__ out) {
    __shared__ float sr[128];
    int d = threadIdx.x;
    sr[d] = g_rels[t * DD + d];
    __syncthreads();
    float s = br[d];
#pragma unroll
    for (int k = 0; k < 128; k++) s += sr[k] * Wr[d * 128 + k];
    out[d] = s;
}

// ---------------- host orchestration --------------------------------------
extern "C" void kernel_launch(void* const* d_in, const int* in_sizes, int n_in,
                              void* d_out, int out_size) {
    const float* feat = (const float*)d_in[0];
    const float* r0 = (const float*)d_in[1];
    const float* r1 = (const float*)d_in[2];
    const float* r2 = (const float*)d_in[3];
    const float* r3 = (const float*)d_in[4];
    const int* eix[4] = {(const int*)d_in[5], (const int*)d_in[6],
                         (const int*)d_in[7], (const int*)d_in[8]};
    const float* gW  = (const float*)d_in[9];
    const float* gb  = (const float*)d_in[10];
    const float* bng = (const float*)d_in[11];
    const float* bnb = (const float*)d_in[12];
    const float* rW  = (const float*)d_in[13];
    const float* rb_ = (const float*)d_in[14];
    float* out = (float*)d_out;

    // degrees + norm coefficients (edges are inputs; recompute every call)
    k_zero_deg<<<(8 * NN + 255) / 256, 256>>>();
    k_deg<<<(4 * NE + 255) / 256, 256>>>(eix[0], eix[1], eix[2], eix[3]);
    k_c<<<(4 * NN + 255) / 256, 256>>>();

    // init evolving state
    k_init<<<(ND / 4 + 255) / 256, 256>>>(feat);
    k_relinit<<<1, 512>>>(r0, r1, r2, r3);

    const int GEMM_BLOCKS = (NN + 127) / 128;     // 391
    const int SCAT_BLOCKS = (NE * 32) / 256;      // 100000
    const int ELEM_BLOCKS = (ND + 255) / 256;     // 25000
    const int STAT_BLOCKS = (NN + 255) / 256;     // 196
    const int ZAGG_BLOCKS = (ND / 4 + 255) / 256; // 6250

    for (int i = 0; i < 2; i++) {
        for (int t = 0; t < 4; t++) {
            k_gemm<<<GEMM_BLOCKS, 256>>>(t, gW + i * DD * DD);
            k_zero_agg<<<ZAGG_BLOCKS, 256>>>();
            k_scatter<<<SCAT_BLOCKS, 256>>>(eix[t], eix[t] + NE);
            k_zero_stats<<<1, 256>>>();
            k_stats<<<STAT_BLOCKS, 256>>>(t, gb + i * DD);
            k_norm<<<ELEM_BLOCKS, 256>>>(t, gb + i * DD, bng + i * DD, bnb + i * DD);
            k_relupd<<<1, 128>>>(t, rW + i * DD * DD, rb_ + i * DD);
        }
    }
    // final layer
    for (int t = 0; t < 4; t++) {
        k_gemm<<<GEMM_BLOCKS, 256>>>(t, gW + 2 * DD * DD);
        k_zero_agg<<<ZAGG_BLOCKS, 256>>>();
        k_scatter<<<SCAT_BLOCKS, 256>>>(eix[t], eix[t] + NE);
        k_finish<<<ELEM_BLOCKS, 256>>>(t, gb + 2 * DD, out + (long)t * ND);
        k_relout<<<1, 128>>>(t, rW + 2 * DD * DD, rb_ + 2 * DD,
                             out + 4L * ND + t * DD);
    }
}

// round 4
// speedup vs baseline: 3.0293x; 2.0568x over previous
#include <cuda_runtime.h>

#define NN 50000
#define NE 800000
#define DD 128
#define ND (NN * DD)          // 6,400,000
#define LSLOPE 0.01f
#define BN_EPS 1e-5f

// ---------------- scratch (device globals; no allocation allowed) ----------
__device__ float g_embs[4 * ND];     // evolving embeddings per relation type
__device__ float g_H[4 * ND];        // GEMM output per type
__device__ float g_Y[4 * ND];        // y = agg*c_dst + b per type
__device__ float g_csrc[4 * NN];
__device__ float g_cdst[4 * NN];
__device__ int   g_cnt_in[4 * NN];
__device__ int   g_cnt_out[4 * NN];
__device__ int   g_cur[4 * NN];
__device__ int   g_off[4 * (NN + 1)];
__device__ int   g_csr[4 * NE];      // src ids grouped by dst
__device__ float g_rels[4 * DD];
__device__ float g_stats[4 * 2 * DD];

// ---------------- CSR build ------------------------------------------------
__global__ void k_zero_hist() {
    int i = blockIdx.x * 256 + threadIdx.x;
    if (i < 4 * NN) { g_cnt_in[i] = 0; g_cnt_out[i] = 0; }
}
__global__ void k_hist(const int* __restrict__ e0, const int* __restrict__ e1,
                       const int* __restrict__ e2, const int* __restrict__ e3) {
    int gid = blockIdx.x * 256 + threadIdx.x;
    if (gid >= 4 * NE) return;
    int t = gid / NE;
    int e = gid - t * NE;
    const int* ei = (t == 0) ? e0 : (t == 1) ? e1 : (t == 2) ? e2 : e3;
    atomicAdd(&g_cnt_out[t * NN + ei[e]], 1);
    atomicAdd(&g_cnt_in[t * NN + ei[NE + e]], 1);
}
// exclusive scan of cnt_in -> off, one block (1024 thr) per type
__global__ void k_scan() {
    int t = blockIdx.x;
    int tid = threadIdx.x;
    __shared__ int sh[1024];
    __shared__ int s_carry;
    if (tid == 0) s_carry = 0;
    __syncthreads();
    for (int chunk = 0; chunk < NN; chunk += 1024) {
        int i = chunk + tid;
        int v = (i < NN) ? g_cnt_in[t * NN + i] : 0;
        sh[tid] = v;
        __syncthreads();
        int val = v;
        for (int ofs = 1; ofs < 1024; ofs <<= 1) {
            int add = (tid >= ofs) ? sh[tid - ofs] : 0;
            __syncthreads();
            val += add;
            sh[tid] = val;
            __syncthreads();
        }
        if (i < NN) g_off[t * (NN + 1) + i] = s_carry + val - v;
        __syncthreads();
        if (tid == 1023) s_carry += val;
        __syncthreads();
    }
    if (tid == 0) g_off[t * (NN + 1) + NN] = s_carry;
}
__global__ void k_c() {
    int gid = blockIdx.x * 256 + threadIdx.x;
    if (gid >= 4 * NN) return;
    int t = gid / NN, v = gid - t * NN;
    int dout = g_cnt_out[gid];
    int din  = g_cnt_in[gid];
    g_csrc[gid] = dout > 0 ? rsqrtf((float)dout) : 1.0f;
    g_cdst[gid] = din  > 0 ? rsqrtf((float)din)  : 1.0f;
    g_cur[gid]  = g_off[t * (NN + 1) + v];
}
__global__ void k_fill(const int* __restrict__ e0, const int* __restrict__ e1,
                       const int* __restrict__ e2, const int* __restrict__ e3) {
    int gid = blockIdx.x * 256 + threadIdx.x;
    if (gid >= 4 * NE) return;
    int t = gid / NE;
    int e = gid - t * NE;
    const int* ei = (t == 0) ? e0 : (t == 1) ? e1 : (t == 2) ? e2 : e3;
    int s = ei[e], d = ei[NE + e];
    int pos = atomicAdd(&g_cur[t * NN + d], 1);
    g_csr[t * NE + pos] = s;
}

// ---------------- init -----------------------------------------------------
__global__ void k_init(const float* __restrict__ feat) {
    int i = blockIdx.x * 256 + threadIdx.x;
    if (i >= ND / 4) return;
    float4 v = ((const float4*)feat)[i];
    ((float4*)g_embs)[0 * (ND / 4) + i] = v;
    ((float4*)g_embs)[1 * (ND / 4) + i] = v;
    ((float4*)g_embs)[2 * (ND / 4) + i] = v;
    ((float4*)g_embs)[3 * (ND / 4) + i] = v;
}
__global__ void k_relinit(const float* __restrict__ r0, const float* __restrict__ r1,
                          const float* __restrict__ r2, const float* __restrict__ r3) {
    int tid = threadIdx.x;
    if (tid >= 512) return;
    int t = tid >> 7, d = tid & 127;
    const float* r = (t == 0) ? r0 : (t == 1) ? r1 : (t == 2) ? r2 : r3;
    g_rels[t * DD + d] = r[d];
}

// ---------------- fused-scale GEMM (batched over types via blockIdx.y) ----
__global__ void __launch_bounds__(256) k_gemm(const float* __restrict__ W) {
    __shared__ float As[128 * 16];
    __shared__ float Bs[16 * 128];
    __shared__ float srel[128];
    const int t = blockIdx.y;
    const float* X  = g_embs + (long)t * ND;
    const float* cs = g_csrc + t * NN;
    const int tid = threadIdx.x;
    const int rb  = blockIdx.x * 128;
    const int tx  = tid & 15, ty = tid >> 4;
    if (tid < 128) srel[tid] = g_rels[t * DD + tid];

    float acc[8][8];
#pragma unroll
    for (int i = 0; i < 8; i++)
#pragma unroll
        for (int j = 0; j < 8; j++) acc[i][j] = 0.f;

    for (int kc = 0; kc < 128; kc += 16) {
        __syncthreads();
#pragma unroll
        for (int u = 0; u < 2; u++) {
            int idx = tid + u * 256;
            int r   = idx >> 2;
            int c4  = (idx & 3) * 4;
            int row = rb + r;
            float4 v = make_float4(0.f, 0.f, 0.f, 0.f);
            if (row < NN) {
                v = *(const float4*)(X + (long)row * 128 + kc + c4);
                float c = cs[row];
                v.x *= c * srel[kc + c4 + 0];
                v.y *= c * srel[kc + c4 + 1];
                v.z *= c * srel[kc + c4 + 2];
                v.w *= c * srel[kc + c4 + 3];
            }
            *(float4*)&As[r * 16 + c4] = v;
        }
#pragma unroll
        for (int u = 0; u < 2; u++) {
            int idx = tid + u * 256;
            int r   = idx >> 5;
            int c4  = (idx & 31) * 4;
            *(float4*)&Bs[r * 128 + c4] = *(const float4*)(W + (long)(kc + r) * 128 + c4);
        }
        __syncthreads();
#pragma unroll
        for (int k = 0; k < 16; k++) {
            float a[8], b[8];
#pragma unroll
            for (int i = 0; i < 8; i++) a[i] = As[(ty * 8 + i) * 16 + k];
            *(float4*)&b[0] = *(float4*)&Bs[k * 128 + tx * 8];
            *(float4*)&b[4] = *(float4*)&Bs[k * 128 + tx * 8 + 4];
#pragma unroll
            for (int i = 0; i < 8; i++)
#pragma unroll
                for (int j = 0; j < 8; j++) acc[i][j] += a[i] * b[j];
        }
    }
    float* H = g_H + (long)t * ND;
#pragma unroll
    for (int i = 0; i < 8; i++) {
        int row = rb + ty * 8 + i;
        if (row < NN) {
            *(float4*)(H + (long)row * 128 + tx * 8) =
                make_float4(acc[i][0], acc[i][1], acc[i][2], acc[i][3]);
            *(float4*)(H + (long)row * 128 + tx * 8 + 4) =
                make_float4(acc[i][4], acc[i][5], acc[i][6], acc[i][7]);
        }
    }
}

// ---------------- CSR gather-reduce: y[d] = (sum_src H[src]) * c_dst + b ---
// One warp per dst node; lane handles 4 floats. No atomics, no zero pass.
// ydst == nullptr -> write to g_Y (device-side symbol resolution; passing
// a __device__ global's address from host code is invalid).
__global__ void __launch_bounds__(256) k_gather(const float* __restrict__ b,
                                                float* ydst) {
    const int t   = blockIdx.y;
    int gid  = blockIdx.x * 256 + threadIdx.x;
    int w    = gid >> 5;
    int lane = gid & 31;
    if (w >= NN) return;
    float* ybase = (ydst == nullptr) ? g_Y : ydst;
    const int* csr = g_csr + (long)t * NE;
    const float* H = g_H + (long)t * ND;
    int beg = g_off[t * (NN + 1) + w];
    int end = g_off[t * (NN + 1) + w + 1];
    float4 a0 = make_float4(0.f, 0.f, 0.f, 0.f);
    float4 a1 = make_float4(0.f, 0.f, 0.f, 0.f);
    for (int base = beg; base < end; base += 32) {
        int idx = base + lane;
        int s_l = (idx < end) ? csr[idx] : 0;
        int cnt = min(32, end - base);
        int j = 0;
        for (; j + 1 < cnt; j += 2) {
            int s0 = __shfl_sync(0xffffffffu, s_l, j);
            int s1 = __shfl_sync(0xffffffffu, s_l, j + 1);
            float4 v0 = *(const float4*)(H + (long)s0 * 128 + lane * 4);
            float4 v1 = *(const float4*)(H + (long)s1 * 128 + lane * 4);
            a0.x += v0.x; a0.y += v0.y; a0.z += v0.z; a0.w += v0.w;
            a1.x += v1.x; a1.y += v1.y; a1.z += v1.z; a1.w += v1.w;
        }
        if (j < cnt) {
            int s0 = __shfl_sync(0xffffffffu, s_l, j);
            float4 v0 = *(const float4*)(H + (long)s0 * 128 + lane * 4);
            a0.x += v0.x; a0.y += v0.y; a0.z += v0.z; a0.w += v0.w;
        }
    }
    float cd = g_cdst[t * NN + w];
    float4 bb = *(const float4*)(b + lane * 4);
    float4 r;
    r.x = (a0.x + a1.x) * cd + bb.x;
    r.y = (a0.y + a1.y) * cd + bb.y;
    r.z = (a0.z + a1.z) * cd + bb.z;
    r.w = (a0.w + a1.w) * cd + bb.w;
    *(float4*)(ybase + (long)t * ND + (long)w * 128 + lane * 4) = r;
}

// ---------------- BN column stats over y (batched over types) -------------
__global__ void k_zero_stats() {
    int i = threadIdx.x;
    if (i < 1024) g_stats[i] = 0.f;
}
__global__ void k_stats() {
    const int t = blockIdx.y;
    const float* Y = g_Y + (long)t * ND;
    int tid  = threadIdx.x;
    int col  = tid & 127;
    int base = blockIdx.x * 256;
    int end  = min(base + 256, NN);
    float s = 0.f, s2 = 0.f;
    for (int r = base + (tid >> 7); r < end; r += 2) {
        float y = Y[(long)r * 128 + col];
        s += y;
        s2 += y * y;
    }
    __shared__ float sh[512];
    sh[tid] = s;
    sh[256 + tid] = s2;
    __syncthreads();
    if (tid < 128) {
        atomicAdd(&g_stats[t * 256 + col],       sh[tid] + sh[tid + 128]);
        atomicAdd(&g_stats[t * 256 + 128 + col], sh[256 + tid] + sh[256 + tid + 128]);
    }
}

// ---------------- BN normalize + leaky residual (float4, batched) ---------
__global__ void k_norm(const float* __restrict__ gamma, const float* __restrict__ beta) {
    const int t = blockIdx.y;
    int i4 = blockIdx.x * 256 + threadIdx.x;
    if (i4 >= ND / 4) return;
    int c = (i4 * 4) & 127;
    float4 y = ((const float4*)(g_Y + (long)t * ND))[i4];
    float4 e = ((const float4*)(g_embs + (long)t * ND))[i4];
    const float inv_n = 1.0f / NN;
#pragma unroll
    for (int u = 0; u < 4; u++) {
        float yv = (&y.x)[u];
        int cc = c + u;
        float mu  = g_stats[t * 256 + cc] * inv_n;
        float var = g_stats[t * 256 + 128 + cc] * inv_n - mu * mu;
        float h = (yv - mu) * rsqrtf(var + BN_EPS) * gamma[cc] + beta[cc];
        h = h > 0.f ? h : LSLOPE * h;
        (&e.x)[u] += h;
    }
    ((float4*)(g_embs + (long)t * ND))[i4] = e;
}

// ---------------- relation vector update (batched over types) -------------
__global__ void k_relupd(const float* __restrict__ Wr, const float* __restrict__ br) {
    const int t = blockIdx.x;
    __shared__ float sr[128];
    int d = threadIdx.x;
    sr[d] = g_rels[t * DD + d];
    __syncthreads();
    float s = br[d];
#pragma unroll
    for (int k = 0; k < 128; k++) s += sr[k] * Wr[d * 128 + k];
    g_rels[t * DD + d] = s;
}
__global__ void k_relout(const float* __restrict__ Wr, const float* __restrict__ br,
                         float* __restrict__ out) {
    const int t = blockIdx.x;
    __shared__ float sr[128];
    int d = threadIdx.x;
    sr[d] = g_rels[t * DD + d];
    __syncthreads();
    float s = br[d];
#pragma unroll
    for (int k = 0; k < 128; k++) s += sr[k] * Wr[d * 128 + k];
    out[t * DD + d] = s;
}

// ---------------- host orchestration --------------------------------------
extern "C" void kernel_launch(void* const* d_in, const int* in_sizes, int n_in,
                              void* d_out, int out_size) {
    const float* feat = (const float*)d_in[0];
    const float* r0 = (const float*)d_in[1];
    const float* r1 = (const float*)d_in[2];
    const float* r2 = (const float*)d_in[3];
    const float* r3 = (const float*)d_in[4];
    const int* e0 = (const int*)d_in[5];
    const int* e1 = (const int*)d_in[6];
    const int* e2 = (const int*)d_in[7];
    const int* e3 = (const int*)d_in[8];
    const float* gW  = (const float*)d_in[9];
    const float* gb  = (const float*)d_in[10];
    const float* bng = (const float*)d_in[11];
    const float* bnb = (const float*)d_in[12];
    const float* rW  = (const float*)d_in[13];
    const float* rb_ = (const float*)d_in[14];
    float* out = (float*)d_out;

    // CSR build (atomics confined here)
    k_zero_hist<<<(4 * NN + 255) / 256, 256>>>();
    k_hist<<<(4 * NE + 255) / 256, 256>>>(e0, e1, e2, e3);
    k_scan<<<4, 1024>>>();
    k_c<<<(4 * NN + 255) / 256, 256>>>();
    k_fill<<<(4 * NE + 255) / 256, 256>>>(e0, e1, e2, e3);

    // init evolving state
    k_init<<<(ND / 4 + 255) / 256, 256>>>(feat);
    k_relinit<<<1, 512>>>(r0, r1, r2, r3);

    const dim3 GEMM_G((NN + 127) / 128, 4);
    const dim3 GATH_G((NN * 32 + 255) / 256, 4);
    const dim3 STAT_G((NN + 255) / 256, 4);
    const dim3 NORM_G((ND / 4 + 255) / 256, 4);

    for (int i = 0; i < 2; i++) {
        k_gemm<<<GEMM_G, 256>>>(gW + i * DD * DD);
        k_gather<<<GATH_G, 256>>>(gb + i * DD, nullptr);   // -> g_Y (device-resolved)
        k_zero_stats<<<1, 1024>>>();
        k_stats<<<STAT_G, 256>>>();
        k_norm<<<NORM_G, 256>>>(bng + i * DD, bnb + i * DD);
        k_relupd<<<4, 128>>>(rW + i * DD * DD, rb_ + i * DD);
    }
    // final layer: gather writes directly to out (real device pointer)
    k_gemm<<<GEMM_G, 256>>>(gW + 2 * DD * DD);
    k_gather<<<GATH_G, 256>>>(gb + 2 * DD, out);
    k_relout<<<4, 128>>>(rW + 2 * DD * DD, rb_ + 2 * DD, out + 4L * ND);
}

// round 7
// speedup vs baseline: 3.5580x; 1.1745x over previous
#include <cuda_runtime.h>
#include <cuda_bf16.h>
#include <cstdint>

#define NN 50000
#define NE 800000
#define DD 128
#define ND (NN * DD)          // 6,400,000
#define LSLOPE 0.01f
#define BN_EPS 1e-5f

// ---------------- scratch (device globals; no allocation allowed) ----------
__device__ float g_embs[4 * ND];
__device__ float g_H[4 * ND];
__device__ float g_Y[4 * ND];
__device__ float g_csrc[4 * NN];
__device__ float g_cdst[4 * NN];
__device__ int   g_cnt_in[4 * NN];
__device__ int   g_cnt_out[4 * NN];
__device__ int   g_cur[4 * NN];
__device__ int   g_off[4 * (NN + 1)];
__device__ int   g_csr[4 * NE];
__device__ float g_rels[4 * DD];
__device__ float g_stats[4 * 2 * DD];
// W split as B[n][kp]: kp = k/2 (uint32 = bf16 pair along k). [128][64] each.
__device__ uint32_t g_Bh[128 * 64];
__device__ uint32_t g_Bl[128 * 64];

// ---------------- CSR build ------------------------------------------------
__global__ void k_zero_hist() {
    int i = blockIdx.x * 256 + threadIdx.x;
    if (i < 4 * NN) { g_cnt_in[i] = 0; g_cnt_out[i] = 0; }
}
__global__ void k_hist(const int* __restrict__ e0, const int* __restrict__ e1,
                       const int* __restrict__ e2, const int* __restrict__ e3) {
    int gid = blockIdx.x * 256 + threadIdx.x;
    if (gid >= 4 * NE) return;
    int t = gid / NE;
    int e = gid - t * NE;
    const int* ei = (t == 0) ? e0 : (t == 1) ? e1 : (t == 2) ? e2 : e3;
    atomicAdd(&g_cnt_out[t * NN + ei[e]], 1);
    atomicAdd(&g_cnt_in[t * NN + ei[NE + e]], 1);
}
__global__ void k_scan() {
    int t = blockIdx.x;
    int tid = threadIdx.x;
    __shared__ int sh[1024];
    __shared__ int s_carry;
    if (tid == 0) s_carry = 0;
    __syncthreads();
    for (int chunk = 0; chunk < NN; chunk += 1024) {
        int i = chunk + tid;
        int v = (i < NN) ? g_cnt_in[t * NN + i] : 0;
        sh[tid] = v;
        __syncthreads();
        int val = v;
        for (int ofs = 1; ofs < 1024; ofs <<= 1) {
            int add = (tid >= ofs) ? sh[tid - ofs] : 0;
            __syncthreads();
            val += add;
            sh[tid] = val;
            __syncthreads();
        }
        if (i < NN) g_off[t * (NN + 1) + i] = s_carry + val - v;
        __syncthreads();
        if (tid == 1023) s_carry += val;
        __syncthreads();
    }
    if (tid == 0) g_off[t * (NN + 1) + NN] = s_carry;
}
__global__ void k_c() {
    int gid = blockIdx.x * 256 + threadIdx.x;
    if (gid >= 4 * NN) return;
    int t = gid / NN, v = gid - t * NN;
    int dout = g_cnt_out[gid];
    int din  = g_cnt_in[gid];
    g_csrc[gid] = dout > 0 ? rsqrtf((float)dout) : 1.0f;
    g_cdst[gid] = din  > 0 ? rsqrtf((float)din)  : 1.0f;
    g_cur[gid]  = g_off[t * (NN + 1) + v];
}
__global__ void k_fill(const int* __restrict__ e0, const int* __restrict__ e1,
                       const int* __restrict__ e2, const int* __restrict__ e3) {
    int gid = blockIdx.x * 256 + threadIdx.x;
    if (gid >= 4 * NE) return;
    int t = gid / NE;
    int e = gid - t * NE;
    const int* ei = (t == 0) ? e0 : (t == 1) ? e1 : (t == 2) ? e2 : e3;
    int s = ei[e], d = ei[NE + e];
    int pos = atomicAdd(&g_cur[t * NN + d], 1);
    g_csr[t * NE + pos] = s;
}

// ---------------- init -----------------------------------------------------
__global__ void k_init(const float* __restrict__ feat) {
    int i = blockIdx.x * 256 + threadIdx.x;
    if (i >= ND / 4) return;
    float4 v = ((const float4*)feat)[i];
    ((float4*)g_embs)[0 * (ND / 4) + i] = v;
    ((float4*)g_embs)[1 * (ND / 4) + i] = v;
    ((float4*)g_embs)[2 * (ND / 4) + i] = v;
    ((float4*)g_embs)[3 * (ND / 4) + i] = v;
}
__global__ void k_relinit(const float* __restrict__ r0, const float* __restrict__ r1,
                          const float* __restrict__ r2, const float* __restrict__ r3) {
    int tid = threadIdx.x;
    if (tid >= 512) return;
    int t = tid >> 7, d = tid & 127;
    const float* r = (t == 0) ? r0 : (t == 1) ? r1 : (t == 2) ? r2 : r3;
    g_rels[t * DD + d] = r[d];
}

// ---------------- W pre-split: B[n][kp] = split(W[k][n]) ------------------
__global__ void k_prepw(const float* __restrict__ W) {
    int slot = blockIdx.x * 256 + threadIdx.x;   // 0..8191
    if (slot >= 128 * 64) return;
    int n  = slot >> 6;
    int kp = slot & 63;
    uint32_t hw = 0, lw = 0;
#pragma unroll
    for (int s = 0; s < 2; s++) {
        float w = W[(kp * 2 + s) * 128 + n];
        __nv_bfloat16 hi = __float2bfloat16(w);
        float rem = w - __bfloat162float(hi);
        __nv_bfloat16 lo = __float2bfloat16(rem);
        hw |= (uint32_t)__bfloat16_as_ushort(hi) << (16 * s);
        lw |= (uint32_t)__bfloat16_as_ushort(lo) << (16 * s);
    }
    g_Bh[slot] = hw;
    g_Bl[slot] = lw;
}

// ---------------- bf16x3 mma.sync GEMM: g_H = (embs*rel*c_src) @ W --------
// 256 thr = 8 warps; warp w owns rows [w*16, w*16+16), all 128 cols.
// K chunked by 32 through SMEM (pad-20 rows: conflict-free fragment loads).
#define MMA_BF16(c, a, b) asm volatile( \
    "mma.sync.aligned.m16n8k16.row.col.f32.bf16.bf16.f32 " \
    "{%0,%1,%2,%3}, {%4,%5,%6,%7}, {%8,%9}, {%0,%1,%2,%3};" \
    : "+f"((c)[0]), "+f"((c)[1]), "+f"((c)[2]), "+f"((c)[3]) \
    : "r"((a)[0]), "r"((a)[1]), "r"((a)[2]), "r"((a)[3]), "r"((b)[0]), "r"((b)[1]))

__global__ void __launch_bounds__(256) k_gemm(int dummy) {
    __shared__ uint32_t As_h[128][20];   // [row][kp], kp=0..15 (k-chunk 32)
    __shared__ uint32_t As_l[128][20];
    __shared__ uint32_t Bs_h[128][20];   // [n][kp]
    __shared__ uint32_t Bs_l[128][20];
    __shared__ float srel[128];
    const int tid  = threadIdx.x;
    const int wid  = tid >> 5;
    const int lane = tid & 31;
    const int t    = blockIdx.y;
    const int rb   = blockIdx.x * 128;
    const float* X  = g_embs + (long)t * ND;
    const float* cs = g_csrc + t * NN;
    if (tid < 128) srel[tid] = g_rels[t * DD + tid];

    float acc[16][4];
#pragma unroll
    for (int nb = 0; nb < 16; nb++)
#pragma unroll
        for (int j = 0; j < 4; j++) acc[nb][j] = 0.f;

    const int r0   = wid * 16 + (lane >> 2);   // fragment row (groupID)
    const int kq   = lane & 3;                 // fragment k-pair index

    for (int kc = 0; kc < 4; kc++) {           // 4 chunks of k=32
        __syncthreads();  // also guards srel on first iter
        // ---- load A chunk: 128 rows x 32 k = 1024 float4 slots
#pragma unroll
        for (int u = 0; u < 4; u++) {
            int slot = tid + u * 256;          // 0..1023
            int row  = slot >> 3;
            int c4   = (slot & 7) * 4;         // local k offset 0..28
            int grow = rb + row;
            uint32_t h0 = 0, h1 = 0, l0 = 0, l1 = 0;
            if (grow < NN) {
                float c = cs[grow];
                float4 v = *(const float4*)(X + (long)grow * 128 + kc * 32 + c4);
                float f[4] = {v.x, v.y, v.z, v.w};
                uint32_t hw[2], lw[2];
#pragma unroll
                for (int jp = 0; jp < 2; jp++) {
                    uint32_t hcur = 0, lcur = 0;
#pragma unroll
                    for (int s = 0; s < 2; s++) {
                        float val = f[jp * 2 + s] * c * srel[kc * 32 + c4 + jp * 2 + s];
                        __nv_bfloat16 hi = __float2bfloat16(val);
                        float rem = val - __bfloat162float(hi);
                        __nv_bfloat16 lo = __float2bfloat16(rem);
                        hcur |= (uint32_t)__bfloat16_as_ushort(hi) << (16 * s);
                        lcur |= (uint32_t)__bfloat16_as_ushort(lo) << (16 * s);
                    }
                    hw[jp] = hcur; lw[jp] = lcur;
                }
                h0 = hw[0]; h1 = hw[1]; l0 = lw[0]; l1 = lw[1];
            }
            int kp = c4 >> 1;                   // 0..14 step 2
            As_h[row][kp] = h0; As_h[row][kp + 1] = h1;
            As_l[row][kp] = l0; As_l[row][kp + 1] = l1;
        }
        // ---- load B chunk: 128 n x 16 kp, from pre-split global
#pragma unroll
        for (int u = 0; u < 8; u++) {
            int slot = tid + u * 256;          // 0..2047
            int n  = slot >> 4;
            int kp = slot & 15;
            Bs_h[n][kp] = g_Bh[n * 64 + kc * 16 + kp];
            Bs_l[n][kp] = g_Bl[n * 64 + kc * 16 + kp];
        }
        __syncthreads();
        // ---- 2 mma k-steps of 16 within this chunk
#pragma unroll
        for (int s = 0; s < 2; s++) {
            uint32_t ah[4], al[4];
            ah[0] = As_h[r0][s * 8 + kq];
            ah[1] = As_h[r0 + 8][s * 8 + kq];
            ah[2] = As_h[r0][s * 8 + 4 + kq];
            ah[3] = As_h[r0 + 8][s * 8 + 4 + kq];
            al[0] = As_l[r0][s * 8 + kq];
            al[1] = As_l[r0 + 8][s * 8 + kq];
            al[2] = As_l[r0][s * 8 + 4 + kq];
            al[3] = As_l[r0 + 8][s * 8 + 4 + kq];
#pragma unroll
            for (int nb = 0; nb < 16; nb++) {
                int n = nb * 8 + (lane >> 2);
                uint32_t bh[2], bl[2];
                bh[0] = Bs_h[n][s * 8 + kq];
                bh[1] = Bs_h[n][s * 8 + 4 + kq];
                bl[0] = Bs_l[n][s * 8 + kq];
                bl[1] = Bs_l[n][s * 8 + 4 + kq];
                MMA_BF16(acc[nb], ah, bh);   // hi*hi
                MMA_BF16(acc[nb], ah, bl);   // hi*lo
                MMA_BF16(acc[nb], al, bh);   // lo*hi
            }
        }
    }
    // ---- epilogue: write 16x128 per warp
    float* H = g_H + (long)t * ND;
    int row_a = rb + r0;
    int row_b = row_a + 8;
    int coff  = (lane & 3) * 2;
#pragma unroll
    for (int nb = 0; nb < 16; nb++) {
        if (row_a < NN)
            *(float2*)(H + (long)row_a * 128 + nb * 8 + coff) =
                make_float2(acc[nb][0], acc[nb][1]);
        if (row_b < NN)
            *(float2*)(H + (long)row_b * 128 + nb * 8 + coff) =
                make_float2(acc[nb][2], acc[nb][3]);
    }
}

// ---------------- CSR gather-reduce ---------------------------------------
__global__ void __launch_bounds__(256) k_gather(const float* __restrict__ b,
                                                float* ydst) {
    const int t   = blockIdx.y;
    int gid  = blockIdx.x * 256 + threadIdx.x;
    int w    = gid >> 5;
    int lane = gid & 31;
    if (w >= NN) return;
    float* ybase = (ydst == nullptr) ? g_Y : ydst;
    const int* csr = g_csr + (long)t * NE;
    const float* H = g_H + (long)t * ND;
    int beg = g_off[t * (NN + 1) + w];
    int end = g_off[t * (NN + 1) + w + 1];
    float4 a0 = make_float4(0.f, 0.f, 0.f, 0.f);
    float4 a1 = make_float4(0.f, 0.f, 0.f, 0.f);
    for (int base = beg; base < end; base += 32) {
        int idx = base + lane;
        int s_l = (idx < end) ? csr[idx] : 0;
        int cnt = min(32, end - base);
        int j = 0;
        for (; j + 1 < cnt; j += 2) {
            int s0 = __shfl_sync(0xffffffffu, s_l, j);
            int s1 = __shfl_sync(0xffffffffu, s_l, j + 1);
            float4 v0 = *(const float4*)(H + (long)s0 * 128 + lane * 4);
            float4 v1 = *(const float4*)(H + (long)s1 * 128 + lane * 4);
            a0.x += v0.x; a0.y += v0.y; a0.z += v0.z; a0.w += v0.w;
            a1.x += v1.x; a1.y += v1.y; a1.z += v1.z; a1.w += v1.w;
        }
        if (j < cnt) {
            int s0 = __shfl_sync(0xffffffffu, s_l, j);
            float4 v0 = *(const float4*)(H + (long)s0 * 128 + lane * 4);
            a0.x += v0.x; a0.y += v0.y; a0.z += v0.z; a0.w += v0.w;
        }
    }
    float cd = g_cdst[t * NN + w];
    float4 bb = *(const float4*)(b + lane * 4);
    float4 r;
    r.x = (a0.x + a1.x) * cd + bb.x;
    r.y = (a0.y + a1.y) * cd + bb.y;
    r.z = (a0.z + a1.z) * cd + bb.z;
    r.w = (a0.w + a1.w) * cd + bb.w;
    *(float4*)(ybase + (long)t * ND + (long)w * 128 + lane * 4) = r;
}

// ---------------- BN stats / normalize ------------------------------------
__global__ void k_zero_stats() {
    int i = threadIdx.x;
    if (i < 1024) g_stats[i] = 0.f;
}
__global__ void k_stats() {
    const int t = blockIdx.y;
    const float* Y = g_Y + (long)t * ND;
    int tid  = threadIdx.x;
    int col  = tid & 127;
    int base = blockIdx.x * 256;
    int end  = min(base + 256, NN);
    float s = 0.f, s2 = 0.f;
    for (int r = base + (tid >> 7); r < end; r += 2) {
        float y = Y[(long)r * 128 + col];
        s += y;
        s2 += y * y;
    }
    __shared__ float sh[512];
    sh[tid] = s;
    sh[256 + tid] = s2;
    __syncthreads();
    if (tid < 128) {
        atomicAdd(&g_stats[t * 256 + col],       sh[tid] + sh[tid + 128]);
        atomicAdd(&g_stats[t * 256 + 128 + col], sh[256 + tid] + sh[256 + tid + 128]);
    }
}
__global__ void k_norm(const float* __restrict__ gamma, const float* __restrict__ beta) {
    const int t = blockIdx.y;
    int i4 = blockIdx.x * 256 + threadIdx.x;
    if (i4 >= ND / 4) return;
    int c = (i4 * 4) & 127;
    float4 y = ((const float4*)(g_Y + (long)t * ND))[i4];
    float4 e = ((const float4*)(g_embs + (long)t * ND))[i4];
    const float inv_n = 1.0f / NN;
#pragma unroll
    for (int u = 0; u < 4; u++) {
        float yv = (&y.x)[u];
        int cc = c + u;
        float mu  = g_stats[t * 256 + cc] * inv_n;
        float var = g_stats[t * 256 + 128 + cc] * inv_n - mu * mu;
        float h = (yv - mu) * rsqrtf(var + BN_EPS) * gamma[cc] + beta[cc];
        h = h > 0.f ? h : LSLOPE * h;
        (&e.x)[u] += h;
    }
    ((float4*)(g_embs + (long)t * ND))[i4] = e;
}

// ---------------- relation vector updates ---------------------------------
__global__ void k_relupd(const float* __restrict__ Wr, const float* __restrict__ br) {
    const int t = blockIdx.x;
    __shared__ float sr[128];
    int d = threadIdx.x;
    sr[d] = g_rels[t * DD + d];
    __syncthreads();
    float s = br[d];
#pragma unroll
    for (int k = 0; k < 128; k++) s += sr[k] * Wr[d * 128 + k];
    g_rels[t * DD + d] = s;
}
__global__ void k_relout(const float* __restrict__ Wr, const float* __restrict__ br,
                         float* __restrict__ out) {
    const int t = blockIdx.x;
    __shared__ float sr[128];
    int d = threadIdx.x;
    sr[d] = g_rels[t * DD + d];
    __syncthreads();
    float s = br[d];
#pragma unroll
    for (int k = 0; k < 128; k++) s += sr[k] * Wr[d * 128 + k];
    out[t * DD + d] = s;
}

// ---------------- host orchestration --------------------------------------
extern "C" void kernel_launch(void* const* d_in, const int* in_sizes, int n_in,
                              void* d_out, int out_size) {
    const float* feat = (const float*)d_in[0];
    const float* r0 = (const float*)d_in[1];
    const float* r1 = (const float*)d_in[2];
    const float* r2 = (const float*)d_in[3];
    const float* r3 = (const float*)d_in[4];
    const int* e0 = (const int*)d_in[5];
    const int* e1 = (const int*)d_in[6];
    const int* e2 = (const int*)d_in[7];
    const int* e3 = (const int*)d_in[8];
    const float* gW  = (const float*)d_in[9];
    const float* gb  = (const float*)d_in[10];
    const float* bng = (const float*)d_in[11];
    const float* bnb = (const float*)d_in[12];
    const float* rW  = (const float*)d_in[13];
    const float* rb_ = (const float*)d_in[14];
    float* out = (float*)d_out;

    // CSR build
    k_zero_hist<<<(4 * NN + 255) / 256, 256>>>();
    k_hist<<<(4 * NE + 255) / 256, 256>>>(e0, e1, e2, e3);
    k_scan<<<4, 1024>>>();
    k_c<<<(4 * NN + 255) / 256, 256>>>();
    k_fill<<<(4 * NE + 255) / 256, 256>>>(e0, e1, e2, e3);

    // init evolving state
    k_init<<<(ND / 4 + 255) / 256, 256>>>(feat);
    k_relinit<<<1, 512>>>(r0, r1, r2, r3);

    const dim3 GEMM_G((NN + 127) / 128, 4);
    const dim3 GATH_G((NN * 32 + 255) / 256, 4);
    const dim3 STAT_G((NN + 255) / 256, 4);
    const dim3 NORM_G((ND / 4 + 255) / 256, 4);

    for (int i = 0; i < 2; i++) {
        k_prepw<<<32, 256>>>(gW + i * DD * DD);
        k_gemm<<<GEMM_G, 256>>>(0);
        k_gather<<<GATH_G, 256>>>(gb + i * DD, nullptr);   // -> g_Y
        k_zero_stats<<<1, 1024>>>();
        k_stats<<<STAT_G, 256>>>();
        k_norm<<<NORM_G, 256>>>(bng + i * DD, bnb + i * DD);
        k_relupd<<<4, 128>>>(rW + i * DD * DD, rb_ + i * DD);
    }
    // final layer
    k_prepw<<<32, 256>>>(gW + 2 * DD * DD);
    k_gemm<<<GEMM_G, 256>>>(0);
    k_gather<<<GATH_G, 256>>>(gb + 2 * DD, out);
    k_relout<<<4, 128>>>(rW + 2 * DD * DD, rb_ + 2 * DD, out + 4L * ND);
}

// round 9
// speedup vs baseline: 3.7068x; 1.0418x over previous
#include <cuda_runtime.h>
#include <cuda_bf16.h>
#include <cuda_fp16.h>
#include <cstdint>

#define NN 50000
#define NE 800000
#define DD 128
#define ND (NN * DD)          // 6,400,000
#define LSLOPE 0.01f
#define BN_EPS 1e-5f

// ---------------- scratch (device globals; no allocation allowed) ----------
__device__ float g_embs[4 * ND];
__device__ float g_H[4 * ND];          // final-layer H (fp32)
__device__ __half2 g_Hh[2 * ND];       // middle-layer H (fp16), 4*ND halves
__device__ float g_Y[4 * ND];
__device__ float g_csrc[4 * NN];
__device__ float g_cdst[4 * NN];
__device__ int   g_cnt_in[4 * NN];
__device__ int   g_cnt_out[4 * NN];
__device__ int   g_cur[4 * NN];
__device__ int   g_off[4 * (NN + 1)];
__device__ int   g_csr[4 * NE];
__device__ float g_rels[4 * DD];
__device__ float g_stats[4 * 2 * DD];
__device__ uint32_t g_Bh[3 * 128 * 64];
__device__ uint32_t g_Bl[3 * 128 * 64];

// ---------------- CSR build ------------------------------------------------
__global__ void k_zero_hist() {
    int i = blockIdx.x * 256 + threadIdx.x;
    if (i < 4 * NN) { g_cnt_in[i] = 0; g_cnt_out[i] = 0; }
}
__global__ void k_hist(const int* __restrict__ e0, const int* __restrict__ e1,
                       const int* __restrict__ e2, const int* __restrict__ e3) {
    int gid = blockIdx.x * 256 + threadIdx.x;
    if (gid >= 4 * NE) return;
    int t = gid / NE;
    int e = gid - t * NE;
    const int* ei = (t == 0) ? e0 : (t == 1) ? e1 : (t == 2) ? e2 : e3;
    atomicAdd(&g_cnt_out[t * NN + ei[e]], 1);
    atomicAdd(&g_cnt_in[t * NN + ei[NE + e]], 1);
}
__global__ void k_scan() {
    int t = blockIdx.x;
    int tid = threadIdx.x;
    __shared__ int sh[1024];
    __shared__ int s_carry;
    if (tid == 0) s_carry = 0;
    __syncthreads();
    for (int chunk = 0; chunk < NN; chunk += 1024) {
        int i = chunk + tid;
        int v = (i < NN) ? g_cnt_in[t * NN + i] : 0;
        sh[tid] = v;
        __syncthreads();
        int val = v;
        for (int ofs = 1; ofs < 1024; ofs <<= 1) {
            int add = (tid >= ofs) ? sh[tid - ofs] : 0;
            __syncthreads();
            val += add;
            sh[tid] = val;
            __syncthreads();
        }
        if (i < NN) g_off[t * (NN + 1) + i] = s_carry + val - v;
        __syncthreads();
        if (tid == 1023) s_carry += val;
        __syncthreads();
    }
    if (tid == 0) g_off[t * (NN + 1) + NN] = s_carry;
}
__global__ void k_c() {
    int gid = blockIdx.x * 256 + threadIdx.x;
    if (gid >= 4 * NN) return;
    int t = gid / NN, v = gid - t * NN;
    int dout = g_cnt_out[gid];
    int din  = g_cnt_in[gid];
    g_csrc[gid] = dout > 0 ? rsqrtf((float)dout) : 1.0f;
    g_cdst[gid] = din  > 0 ? rsqrtf((float)din)  : 1.0f;
    g_cur[gid]  = g_off[t * (NN + 1) + v];
}
__global__ void k_fill(const int* __restrict__ e0, const int* __restrict__ e1,
                       const int* __restrict__ e2, const int* __restrict__ e3) {
    int gid = blockIdx.x * 256 + threadIdx.x;
    if (gid >= 4 * NE) return;
    int t = gid / NE;
    int e = gid - t * NE;
    const int* ei = (t == 0) ? e0 : (t == 1) ? e1 : (t == 2) ? e2 : e3;
    int s = ei[e], d = ei[NE + e];
    int pos = atomicAdd(&g_cur[t * NN + d], 1);
    g_csr[t * NE + pos] = s;
}

// ---------------- init -----------------------------------------------------
__global__ void k_init(const float* __restrict__ feat) {
    int i = blockIdx.x * 256 + threadIdx.x;
    if (i >= ND / 4) return;
    float4 v = ((const float4*)feat)[i];
    ((float4*)g_embs)[0 * (ND / 4) + i] = v;
    ((float4*)g_embs)[1 * (ND / 4) + i] = v;
    ((float4*)g_embs)[2 * (ND / 4) + i] = v;
    ((float4*)g_embs)[3 * (ND / 4) + i] = v;
}
__global__ void k_relinit(const float* __restrict__ r0, const float* __restrict__ r1,
                          const float* __restrict__ r2, const float* __restrict__ r3) {
    int tid = threadIdx.x;
    if (tid >= 512) return;
    int t = tid >> 7, d = tid & 127;
    const float* r = (t == 0) ? r0 : (t == 1) ? r1 : (t == 2) ? r2 : r3;
    g_rels[t * DD + d] = r[d];
}

// ---------------- W pre-split (all 3 layers): B[l][n][kp] -----------------
__global__ void k_prepw(const float* __restrict__ gW) {
    int layer = blockIdx.y;
    int slot = blockIdx.x * 256 + threadIdx.x;
    if (slot >= 128 * 64) return;
    const float* W = gW + layer * DD * DD;
    int n  = slot >> 6;
    int kp = slot & 63;
    uint32_t hw = 0, lw = 0;
#pragma unroll
    for (int s = 0; s < 2; s++) {
        float w = W[(kp * 2 + s) * 128 + n];
        __nv_bfloat16 hi = __float2bfloat16(w);
        float rem = w - __bfloat162float(hi);
        __nv_bfloat16 lo = __float2bfloat16(rem);
        hw |= (uint32_t)__bfloat16_as_ushort(hi) << (16 * s);
        lw |= (uint32_t)__bfloat16_as_ushort(lo) << (16 * s);
    }
    g_Bh[layer * 8192 + slot] = hw;
    g_Bl[layer * 8192 + slot] = lw;
}

// ---------------- bf16x3 mma.sync GEMM with fused BN/residual A-load ------
#define MMA_BF16(c, a, b) asm volatile( \
    "mma.sync.aligned.m16n8k16.row.col.f32.bf16.bf16.f32 " \
    "{%0,%1,%2,%3}, {%4,%5,%6,%7}, {%8,%9}, {%0,%1,%2,%3};" \
    : "+f"((c)[0]), "+f"((c)[1]), "+f"((c)[2]), "+f"((c)[3]) \
    : "r"((a)[0]), "r"((a)[1]), "r"((a)[2]), "r"((a)[3]), "r"((b)[0]), "r"((b)[1]))

__global__ void __launch_bounds__(256) k_gemm(int layer,
                                              const float* __restrict__ gamma,
                                              const float* __restrict__ beta) {
    __shared__ uint32_t As_h[128][20];
    __shared__ uint32_t As_l[128][20];
    __shared__ uint32_t Bs_h[128][20];
    __shared__ uint32_t Bs_l[128][20];
    __shared__ float srel[128];
    __shared__ float s_a[128];    // BN scale per feature
    __shared__ float s_sh[128];   // BN shift per feature
    const int tid  = threadIdx.x;
    const int wid  = tid >> 5;
    const int lane = tid & 31;
    const int t    = blockIdx.y;
    const int rb   = blockIdx.x * 128;
    float* Xm = g_embs + (long)t * ND;
    const float* Yt = g_Y + (long)t * ND;
    const float* cs = g_csrc + t * NN;
    const uint32_t* Bhb = g_Bh + layer * 8192;
    const uint32_t* Blb = g_Bl + layer * 8192;
    if (tid < 128) {
        srel[tid] = g_rels[t * DD + tid];
        if (layer > 0) {
            float mu  = g_stats[t * 256 + tid] * (1.0f / NN);
            float var = g_stats[t * 256 + 128 + tid] * (1.0f / NN) - mu * mu;
            float a = rsqrtf(var + BN_EPS) * gamma[tid];
            s_a[tid]  = a;
            s_sh[tid] = beta[tid] - mu * a;
        }
    }

    float acc[16][4];
#pragma unroll
    for (int nb = 0; nb < 16; nb++)
#pragma unroll
        for (int j = 0; j < 4; j++) acc[nb][j] = 0.f;

    const int r0 = wid * 16 + (lane >> 2);
    const int kq = lane & 3;

    for (int kc = 0; kc < 4; kc++) {
        __syncthreads();  // also guards srel/s_a/s_sh on first iter
#pragma unroll
        for (int u = 0; u < 4; u++) {
            int slot = tid + u * 256;
            int row  = slot >> 3;
            int c4   = (slot & 7) * 4;
            int grow = rb + row;
            uint32_t h0 = 0, h1 = 0, l0 = 0, l1 = 0;
            if (grow < NN) {
                float c = cs[grow];
                float* xp = Xm + (long)grow * 128 + kc * 32 + c4;
                float4 v = *(const float4*)xp;
                if (layer > 0) {   // fused BN + leaky + residual (exclusive row owner)
                    float4 yv = *(const float4*)(Yt + (long)grow * 128 + kc * 32 + c4);
#pragma unroll
                    for (int uu = 0; uu < 4; uu++) {
                        int k = kc * 32 + c4 + uu;
                        float h = (&yv.x)[uu] * s_a[k] + s_sh[k];
                        h = h > 0.f ? h : LSLOPE * h;
                        (&v.x)[uu] += h;
                    }
                    *(float4*)xp = v;   // write e_new back
                }
                float f[4] = {v.x, v.y, v.z, v.w};
                uint32_t hw[2], lw[2];
#pragma unroll
                for (int jp = 0; jp < 2; jp++) {
                    uint32_t hcur = 0, lcur = 0;
#pragma unroll
                    for (int s = 0; s < 2; s++) {
                        float val = f[jp * 2 + s] * c * srel[kc * 32 + c4 + jp * 2 + s];
                        __nv_bfloat16 hi = __float2bfloat16(val);
                        float rem = val - __bfloat162float(hi);
                        __nv_bfloat16 lo = __float2bfloat16(rem);
                        hcur |= (uint32_t)__bfloat16_as_ushort(hi) << (16 * s);
                        lcur |= (uint32_t)__bfloat16_as_ushort(lo) << (16 * s);
                    }
                    hw[jp] = hcur; lw[jp] = lcur;
                }
                h0 = hw[0]; h1 = hw[1]; l0 = lw[0]; l1 = lw[1];
            }
            int kp = c4 >> 1;
            As_h[row][kp] = h0; As_h[row][kp + 1] = h1;
            As_l[row][kp] = l0; As_l[row][kp + 1] = l1;
        }
#pragma unroll
        for (int u = 0; u < 8; u++) {
            int slot = tid + u * 256;
            int n  = slot >> 4;
            int kp = slot & 15;
            Bs_h[n][kp] = Bhb[n * 64 + kc * 16 + kp];
            Bs_l[n][kp] = Blb[n * 64 + kc * 16 + kp];
        }
        __syncthreads();
#pragma unroll
        for (int s = 0; s < 2; s++) {
            uint32_t ah[4], al[4];
            ah[0] = As_h[r0][s * 8 + kq];
            ah[1] = As_h[r0 + 8][s * 8 + kq];
            ah[2] = As_h[r0][s * 8 + 4 + kq];
            ah[3] = As_h[r0 + 8][s * 8 + 4 + kq];
            al[0] = As_l[r0][s * 8 + kq];
            al[1] = As_l[r0 + 8][s * 8 + kq];
            al[2] = As_l[r0][s * 8 + 4 + kq];
            al[3] = As_l[r0 + 8][s * 8 + 4 + kq];
#pragma unroll
            for (int nb = 0; nb < 16; nb++) {
                int n = nb * 8 + (lane >> 2);
                uint32_t bh[2], bl[2];
                bh[0] = Bs_h[n][s * 8 + kq];
                bh[1] = Bs_h[n][s * 8 + 4 + kq];
                bl[0] = Bs_l[n][s * 8 + kq];
                bl[1] = Bs_l[n][s * 8 + 4 + kq];
                MMA_BF16(acc[nb], ah, bh);
                MMA_BF16(acc[nb], ah, bl);
                MMA_BF16(acc[nb], al, bh);
            }
        }
    }
    int row_a = rb + r0;
    int row_b = row_a + 8;
    int coff  = (lane & 3) * 2;
    if (layer < 2) {   // middle layers: fp16 H
        __half2* Hh = g_Hh + (long)t * (ND / 2);
#pragma unroll
        for (int nb = 0; nb < 16; nb++) {
            int h2i = (nb * 8 + coff) >> 1;
            if (row_a < NN)
                Hh[(long)row_a * 64 + h2i] = __floats2half2_rn(acc[nb][0], acc[nb][1]);
            if (row_b < NN)
                Hh[(long)row_b * 64 + h2i] = __floats2half2_rn(acc[nb][2], acc[nb][3]);
        }
    } else {           // final layer: fp32 H
        float* H = g_H + (long)t * ND;
#pragma unroll
        for (int nb = 0; nb < 16; nb++) {
            if (row_a < NN)
                *(float2*)(H + (long)row_a * 128 + nb * 8 + coff) =
                    make_float2(acc[nb][0], acc[nb][1]);
            if (row_b < NN)
                *(float2*)(H + (long)row_b * 128 + nb * 8 + coff) =
                    make_float2(acc[nb][2], acc[nb][3]);
        }
    }
}

// ---------------- CSR gather (fp16 H, middle layers) -> g_Y ---------------
__global__ void __launch_bounds__(256) k_gather_h(const float* __restrict__ b) {
    const int t = blockIdx.y;
    int gid  = blockIdx.x * 256 + threadIdx.x;
    int w    = gid >> 5;
    int lane = gid & 31;
    if (w >= NN) return;
    const int* csr = g_csr + (long)t * NE;
    const uint2* Hh = (const uint2*)(g_Hh + (long)t * (ND / 2));  // 32 uint2/row
    int beg = g_off[t * (NN + 1) + w];
    int end = g_off[t * (NN + 1) + w + 1];
    float4 a0 = make_float4(0.f, 0.f, 0.f, 0.f);
    float4 a1 = make_float4(0.f, 0.f, 0.f, 0.f);
    for (int base = beg; base < end; base += 32) {
        int idx = base + lane;
        int s_l = (idx < end) ? csr[idx] : 0;
        int cnt = min(32, end - base);
        int j = 0;
        for (; j + 1 < cnt; j += 2) {
            int s0 = __shfl_sync(0xffffffffu, s_l, j);
            int s1 = __shfl_sync(0xffffffffu, s_l, j + 1);
            uint2 u0 = Hh[(long)s0 * 32 + lane];
            uint2 u1 = Hh[(long)s1 * 32 + lane];
            float2 f0 = __half22float2(*(__half2*)&u0.x);
            float2 f1 = __half22float2(*(__half2*)&u0.y);
            float2 f2 = __half22float2(*(__half2*)&u1.x);
            float2 f3 = __half22float2(*(__half2*)&u1.y);
            a0.x += f0.x; a0.y += f0.y; a0.z += f1.x; a0.w += f1.y;
            a1.x += f2.x; a1.y += f2.y; a1.z += f3.x; a1.w += f3.y;
        }
        if (j < cnt) {
            int s0 = __shfl_sync(0xffffffffu, s_l, j);
            uint2 u0 = Hh[(long)s0 * 32 + lane];
            float2 f0 = __half22float2(*(__half2*)&u0.x);
            float2 f1 = __half22float2(*(__half2*)&u0.y);
            a0.x += f0.x; a0.y += f0.y; a0.z += f1.x; a0.w += f1.y;
        }
    }
    float cd = g_cdst[t * NN + w];
    float4 bb = *(const float4*)(b + lane * 4);
    float4 r;
    r.x = (a0.x + a1.x) * cd + bb.x;
    r.y = (a0.y + a1.y) * cd + bb.y;
    r.z = (a0.z + a1.z) * cd + bb.z;
    r.w = (a0.w + a1.w) * cd + bb.w;
    *(float4*)(g_Y + (long)t * ND + (long)w * 128 + lane * 4) = r;
}

// ---------------- CSR gather (fp32 H, final layer) -> out -----------------
__global__ void __launch_bounds__(256) k_gather_f(const float* __restrict__ b,
                                                  float* __restrict__ out) {
    const int t = blockIdx.y;
    int gid  = blockIdx.x * 256 + threadIdx.x;
    int w    = gid >> 5;
    int lane = gid & 31;
    if (w >= NN) return;
    const int* csr = g_csr + (long)t * NE;
    const float* H = g_H + (long)t * ND;
    int beg = g_off[t * (NN + 1) + w];
    int end = g_off[t * (NN + 1) + w + 1];
    float4 a0 = make_float4(0.f, 0.f, 0.f, 0.f);
    float4 a1 = make_float4(0.f, 0.f, 0.f, 0.f);
    for (int base = beg; base < end; base += 32) {
        int idx = base + lane;
        int s_l = (idx < end) ? csr[idx] : 0;
        int cnt = min(32, end - base);
        int j = 0;
        for (; j + 1 < cnt; j += 2) {
            int s0 = __shfl_sync(0xffffffffu, s_l, j);
            int s1 = __shfl_sync(0xffffffffu, s_l, j + 1);
            float4 v0 = *(const float4*)(H + (long)s0 * 128 + lane * 4);
            float4 v1 = *(const float4*)(H + (long)s1 * 128 + lane * 4);
            a0.x += v0.x; a0.y += v0.y; a0.z += v0.z; a0.w += v0.w;
            a1.x += v1.x; a1.y += v1.y; a1.z += v1.z; a1.w += v1.w;
        }
        if (j < cnt) {
            int s0 = __shfl_sync(0xffffffffu, s_l, j);
            float4 v0 = *(const float4*)(H + (long)s0 * 128 + lane * 4);
            a0.x += v0.x; a0.y += v0.y; a0.z += v0.z; a0.w += v0.w;
        }
    }
    float cd = g_cdst[t * NN + w];
    float4 bb = *(const float4*)(b + lane * 4);
    float4 r;
    r.x = (a0.x + a1.x) * cd + bb.x;
    r.y = (a0.y + a1.y) * cd + bb.y;
    r.z = (a0.z + a1.z) * cd + bb.z;
    r.w = (a0.w + a1.w) * cd + bb.w;
    *(float4*)(out + (long)t * ND + (long)w * 128 + lane * 4) = r;
}

// ---------------- BN stats -------------------------------------------------
__global__ void k_zero_stats() {
    int i = threadIdx.x;
    if (i < 1024) g_stats[i] = 0.f;
}
__global__ void k_stats() {
    const int t = blockIdx.y;
    const float* Y = g_Y + (long)t * ND;
    int tid  = threadIdx.x;
    int col  = tid & 127;
    int base = blockIdx.x * 256;
    int end  = min(base + 256, NN);
    float s = 0.f, s2 = 0.f;
    for (int r = base + (tid >> 7); r < end; r += 2) {
        float y = Y[(long)r * 128 + col];
        s += y;
        s2 += y * y;
    }
    __shared__ float sh[512];
    sh[tid] = s;
    sh[256 + tid] = s2;
    __syncthreads();
    if (tid < 128) {
        atomicAdd(&g_stats[t * 256 + col],       sh[tid] + sh[tid + 128]);
        atomicAdd(&g_stats[t * 256 + 128 + col], sh[256 + tid] + sh[256 + tid + 128]);
    }
}

// ---------------- relation vector updates ---------------------------------
__global__ void k_relupd(const float* __restrict__ Wr, const float* __restrict__ br) {
    const int t = blockIdx.x;
    __shared__ float sr[128];
    int d = threadIdx.x;
    sr[d] = g_rels[t * DD + d];
    __syncthreads();
    float s = br[d];
#pragma unroll
    for (int k = 0; k < 128; k++) s += sr[k] * Wr[d * 128 + k];
    g_rels[t * DD + d] = s;
}
__global__ void k_relout(const float* __restrict__ Wr, const float* __restrict__ br,
                         float* __restrict__ out) {
    const int t = blockIdx.x;
    __shared__ float sr[128];
    int d = threadIdx.x;
    sr[d] = g_rels[t * DD + d];
    __syncthreads();
    float s = br[d];
#pragma unroll
    for (int k = 0; k < 128; k++) s += sr[k] * Wr[d * 128 + k];
    out[t * DD + d] = s;
}

// ---------------- host orchestration --------------------------------------
extern "C" void kernel_launch(void* const* d_in, const int* in_sizes, int n_in,
                              void* d_out, int out_size) {
    const float* feat = (const float*)d_in[0];
    const float* r0 = (const float*)d_in[1];
    const float* r1 = (const float*)d_in[2];
    const float* r2 = (const float*)d_in[3];
    const float* r3 = (const float*)d_in[4];
    const int* e0 = (const int*)d_in[5];
    const int* e1 = (const int*)d_in[6];
    const int* e2 = (const int*)d_in[7];
    const int* e3 = (const int*)d_in[8];
    const float* gW  = (const float*)d_in[9];
    const float* gb  = (const float*)d_in[10];
    const float* bng = (const float*)d_in[11];
    const float* bnb = (const float*)d_in[12];
    const float* rW  = (const float*)d_in[13];
    const float* rb_ = (const float*)d_in[14];
    float* out = (float*)d_out;

    // setup
    k_zero_hist<<<(4 * NN + 255) / 256, 256>>>();
    k_hist<<<(4 * NE + 255) / 256, 256>>>(e0, e1, e2, e3);
    k_scan<<<4, 1024>>>();
    k_c<<<(4 * NN + 255) / 256, 256>>>();
    k_fill<<<(4 * NE + 255) / 256, 256>>>(e0, e1, e2, e3);
    k_init<<<(ND / 4 + 255) / 256, 256>>>(feat);
    k_relinit<<<1, 512>>>(r0, r1, r2, r3);
    {
        dim3 g(32, 3);
        k_prepw<<<g, 256>>>(gW);
    }

    const dim3 GEMM_G((NN + 127) / 128, 4);
    const dim3 GATH_G((NN * 32 + 255) / 256, 4);
    const dim3 STAT_G((NN + 255) / 256, 4);

    // conv 0 (no fused norm; fp16 H)
    k_gemm<<<GEMM_G, 256>>>(0, nullptr, nullptr);
    k_relupd<<<4, 128>>>(rW + 0 * DD * DD, rb_ + 0 * DD);
    k_gather_h<<<GATH_G, 256>>>(gb + 0 * DD);
    k_zero_stats<<<1, 1024>>>();
    k_stats<<<STAT_G, 256>>>();
    // conv 1 (fuses BN0+residual into A-load; fp16 H)
    k_gemm<<<GEMM_G, 256>>>(1, bng + 0 * DD, bnb + 0 * DD);
    k_relupd<<<4, 128>>>(rW + 1 * DD * DD, rb_ + 1 * DD);
    k_gather_h<<<GATH_G, 256>>>(gb + 1 * DD);
    k_zero_stats<<<1, 1024>>>();
    k_stats<<<STAT_G, 256>>>();
    // conv 2 (fuses BN1+residual; fp32 H -> out)
    k_gemm<<<GEMM_G, 256>>>(2, bng + 1 * DD, bnb + 1 * DD);
    k_relout<<<4, 128>>>(rW + 2 * DD * DD, rb_ + 2 * DD, out + 4L * ND);
    k_gather_f<<<GATH_G, 256>>>(gb + 2 * DD, out);
}